// round 16
// baseline (speedup 1.0000x reference)
#include <cuda_runtime.h>
#include <cuda_fp16.h>
#include <cstdint>

#define N_NODES  40000
#define N_EDGES  640000
#define N_GRAPHS 256
#define NB 157            // ceil(40000/256) scan blocks
#define CSR_CAP 760000    // N_EDGES + N_NODES*3 worst-case pad-to-4
#define GEMM1_BLOCKS 313  // ceil(40000/128)
#define FILL_BLOCKS 313   // ceil(160000/512)

// ---------------- scratch (static __device__, no allocation) ----------------
__device__ __align__(16) int    g_degi[N_NODES];
__device__ __align__(16) int    g_rowstart[N_NODES];
__device__ __align__(16) int    g_cursor[N_NODES];
__device__ __align__(16) int    g_csr[CSR_CAP];
__device__ int    g_base;
__device__ __align__(16) float  g_dis[N_NODES];
__device__ __align__(16) __half g_xh[N_NODES * 128];
__device__ __align__(16) __half g_w1h[128 * 128];
__device__ __align__(16) __half g_w2h[128 * 64];
__device__ __align__(16) __half g_w3h[64 * 32];
__device__ __align__(16) __half g_h1[N_NODES * 128];
__device__ __align__(16) __half g_h2[N_NODES * 64];
__device__ __align__(16) __half g_h3[N_NODES * 32];
__device__ __align__(16) float  g_pooled[N_GRAPHS * 32];
__device__ __align__(16) float  g_cnt[N_GRAPHS];

// ---------------- helpers ----------------
__device__ __forceinline__ void red_add_v4(float* addr, float4 v) {
    asm volatile("red.global.add.v4.f32 [%0], {%1, %2, %3, %4};"
                 :: "l"(addr), "f"(v.x), "f"(v.y), "f"(v.z), "f"(v.w)
                 : "memory");
}
__device__ __forceinline__ unsigned h2_bits(__half2 h) {
    unsigned u;
    *(__half2*)&u = h;
    return u;
}
__device__ __forceinline__ uint4 cvt8(float4 a, float4 b) {
    uint4 o;
    o.x = h2_bits(__floats2half2_rn(a.x, a.y));
    o.y = h2_bits(__floats2half2_rn(a.z, a.w));
    o.z = h2_bits(__floats2half2_rn(b.x, b.y));
    o.w = h2_bits(__floats2half2_rn(b.z, b.w));
    return o;
}
__device__ __forceinline__ void acc_add(float2 acc[4], uint4 v) {
    __half2* p = (__half2*)&v;
    #pragma unroll
    for (int k = 0; k < 4; k++) {
        float2 f = __half22float2(p[k]);
        acc[k].x += f.x; acc[k].y += f.y;
    }
}
__device__ __forceinline__ void ldsm_x4(unsigned* r, const __half* p) {
    unsigned a = (unsigned)__cvta_generic_to_shared(p);
    asm volatile("ldmatrix.sync.aligned.m8n8.x4.shared.b16 {%0,%1,%2,%3}, [%4];"
                 : "=r"(r[0]), "=r"(r[1]), "=r"(r[2]), "=r"(r[3]) : "r"(a));
}
__device__ __forceinline__ void ldsm_x4_t(unsigned* r, const __half* p) {
    unsigned a = (unsigned)__cvta_generic_to_shared(p);
    asm volatile("ldmatrix.sync.aligned.m8n8.x4.trans.shared.b16 {%0,%1,%2,%3}, [%4];"
                 : "=r"(r[0]), "=r"(r[1]), "=r"(r[2]), "=r"(r[3]) : "r"(a));
}
__device__ __forceinline__ void mma16816(float* d, const unsigned* a, const unsigned* b) {
    asm volatile(
        "mma.sync.aligned.m16n8k16.row.col.f32.f16.f16.f32 "
        "{%0,%1,%2,%3}, {%4,%5,%6,%7}, {%8,%9}, {%0,%1,%2,%3};"
        : "+f"(d[0]), "+f"(d[1]), "+f"(d[2]), "+f"(d[3])
        : "r"(a[0]), "r"(a[1]), "r"(a[2]), "r"(a[3]), "r"(b[0]), "r"(b[1]));
}

// ---------------- prep ----------------
// zero scratch + convert all three W matrices to fp16 (no extra launch)
__global__ void k_zero(const float* __restrict__ W1, const float* __restrict__ W2,
                       const float* __restrict__ W3) {
    int i = blockIdx.x * blockDim.x + threadIdx.x;
    if (i < N_NODES) g_degi[i] = 0;
    if (i < N_GRAPHS * 32) g_pooled[i] = 0.f;
    if (i < N_GRAPHS) g_cnt[i] = 0.f;
    if (i == 0) g_base = 0;
    if (i < 8192)
        ((__half2*)g_w1h)[i] = __float22half2_rn(((const float2*)W1)[i]);
    else if (i < 12288)
        ((__half2*)g_w2h)[i - 8192] = __float22half2_rn(((const float2*)W2)[i - 8192]);
    else if (i < 13312)
        ((__half2*)g_w3h)[i - 12288] = __float22half2_rn(((const float2*)W3)[i - 12288]);
}

// degree count + batch count + x fp32->fp16 convert (atomic latency overlapped
// with streaming conversion). grid 625*256 = 160000 threads.
__global__ void k_count(const int* __restrict__ ei, const int* __restrict__ batch,
                        const float* __restrict__ x) {
    int i = blockIdx.x * blockDim.x + threadIdx.x;
    int4 d4 = ((const int4*)(ei + N_EDGES))[i];
    atomicAdd(&g_degi[d4.x], 1);
    atomicAdd(&g_degi[d4.y], 1);
    atomicAdd(&g_degi[d4.z], 1);
    atomicAdd(&g_degi[d4.w], 1);
    if (i < N_NODES) atomicAdd(&g_cnt[batch[i]], 1.0f);
    #pragma unroll
    for (int j = 0; j < 4; j++) {
        int idx = i + j * 160000;              // 640000 uint4 total
        float4 a = ((const float4*)x)[(size_t)idx * 2];
        float4 b = ((const float4*)x)[(size_t)idx * 2 + 1];
        ((uint4*)g_xh)[idx] = cvt8(a, b);
    }
}

// single-kernel scan over PADDED degrees (segments rounded to 4 ints)
__global__ void k_scan() {
    int t = threadIdx.x, i = blockIdx.x * 256 + t;
    int lane = t & 31, w = t >> 5;
    int v  = (i < N_NODES) ? g_degi[i] : 0;
    int pv = (v + 3) & ~3;

    int sv = pv;
    #pragma unroll
    for (int off = 1; off < 32; off <<= 1) {
        int n = __shfl_up_sync(0xffffffffu, sv, off);
        if (lane >= off) sv += n;
    }
    __shared__ int ws[8];
    if (lane == 31) ws[w] = sv;
    __syncthreads();
    if (w == 0 && lane < 8) {
        int x = ws[lane];
        #pragma unroll
        for (int off = 1; off < 8; off <<= 1) {
            int n = __shfl_up_sync(0xffu, x, off);
            if (lane >= off) x += n;
        }
        ws[lane] = x;
    }
    __syncthreads();
    int incl = sv + (w ? ws[w - 1] : 0);

    __shared__ int base;
    if (t == 255) base = atomicAdd(&g_base, incl);
    __syncthreads();

    if (i < N_NODES) {
        int ex = base + incl - pv;
        g_rowstart[i] = ex;
        g_cursor[i]   = ex;
        g_dis[i]      = rsqrtf((float)v + 1.0f);
    }
}

// ---------------- GEMM compute phase (smem tiles -> global fp16 out) --------
template<int K, int N, int WM, int WN, int THREADS>
__device__ __forceinline__ void gemm_compute(const __half* Xs, const __half* Ws,
                                             __half* __restrict__ out, int row0) {
    constexpr int MT  = 128;
    constexpr int XS  = K + 8;
    constexpr int WS  = N + 8;
    constexpr int MW  = MT / WM;
    constexpr int NW  = N / WN;
    constexpr int MTL = MW / 16;
    constexpr int NTL = NW / 8;
    static_assert(WM * WN == THREADS / 32, "warp layout");
    static_assert(MTL >= 1 && NTL >= 2 && NTL % 2 == 0, "tile shape");

    int rows = N_NODES - row0; if (rows > MT) rows = MT;
    int tid = threadIdx.x;
    int wid = tid >> 5, lane = tid & 31;
    int wm = wid % WM, wn = wid / WM;
    int mbase = wm * MW, nbase = wn * NW;

    float acc[MTL][NTL][4];
    #pragma unroll
    for (int mt = 0; mt < MTL; mt++)
        #pragma unroll
        for (int nt = 0; nt < NTL; nt++)
            acc[mt][nt][0] = acc[mt][nt][1] = acc[mt][nt][2] = acc[mt][nt][3] = 0.f;

    #pragma unroll
    for (int k0 = 0; k0 < K; k0 += 16) {
        unsigned af[MTL][4];
        unsigned bf[NTL][2];
        #pragma unroll
        for (int mt = 0; mt < MTL; mt++) {
            const __half* p = Xs + (mbase + mt * 16 + (lane & 15)) * XS
                                 + k0 + ((lane >> 4) << 3);
            ldsm_x4(af[mt], p);
        }
        #pragma unroll
        for (int p2 = 0; p2 < NTL / 2; p2++) {
            const __half* p = Ws + (k0 + (lane & 15)) * WS
                                 + nbase + p2 * 16 + ((lane >> 4) << 3);
            ldsm_x4_t(&bf[p2 * 2][0], p);
        }
        #pragma unroll
        for (int mt = 0; mt < MTL; mt++)
            #pragma unroll
            for (int nt = 0; nt < NTL; nt++)
                mma16816(acc[mt][nt], af[mt], bf[nt]);
    }

    int gr = lane >> 2, tc = (lane & 3) << 1;
    #pragma unroll
    for (int mt = 0; mt < MTL; mt++) {
        int rA = mbase + mt * 16 + gr;
        int rB = rA + 8;
        bool okA = rA < rows, okB = rB < rows;
        float dA = okA ? g_dis[row0 + rA] : 0.f;
        float dB = okB ? g_dis[row0 + rB] : 0.f;
        #pragma unroll
        for (int nt = 0; nt < NTL; nt++) {
            int col = nbase + nt * 8 + tc;
            if (okA)
                *(__half2*)(out + (size_t)(row0 + rA) * N + col) =
                    __floats2half2_rn(acc[mt][nt][0] * dA, acc[mt][nt][1] * dA);
            if (okB)
                *(__half2*)(out + (size_t)(row0 + rB) * N + col) =
                    __floats2half2_rn(acc[mt][nt][2] * dB, acc[mt][nt][3] * dB);
        }
    }
}

// ---------------- layer-1 GEMM body (fp16 in, fp16 W, global->smem->mma) ----
template<int K, int N, int WM, int WN, int THREADS>
__device__ __forceinline__ void gemm_body(const __half* __restrict__ in,
                                          const __half* __restrict__ W,
                                          __half* __restrict__ out,
                                          int tile, __half* sm) {
    constexpr int MT  = 128;
    constexpr int XS  = K + 8;
    constexpr int WS  = N + 8;
    constexpr int XLD = MT * (K / 8) / THREADS;
    constexpr int WLD = K * (N / 8) / THREADS;

    __half* Xs = sm;
    __half* Ws = sm + MT * XS;

    int tid  = threadIdx.x;
    int row0 = tile * MT;
    int rows = N_NODES - row0; if (rows > MT) rows = MT;

    uint4 xv[XLD];
    #pragma unroll
    for (int j = 0; j < XLD; j++) {
        int i = tid + j * THREADS;
        int r = i / (K / 8);
        xv[j] = make_uint4(0, 0, 0, 0);
        if (r < rows)
            xv[j] = ((const uint4*)in)[(size_t)row0 * (K / 8) + i];
    }
    uint4 wv[WLD];
    #pragma unroll
    for (int j = 0; j < WLD; j++)
        wv[j] = ((const uint4*)W)[tid + j * THREADS];

    #pragma unroll
    for (int j = 0; j < XLD; j++) {
        int i = tid + j * THREADS;
        int r = i / (K / 8), c = i % (K / 8);
        *(uint4*)(Xs + r * XS + c * 8) = xv[j];
    }
    #pragma unroll
    for (int j = 0; j < WLD; j++) {
        int i = tid + j * THREADS;
        int k = i / (N / 8), c = i % (N / 8);
        *(uint4*)(Ws + k * WS + c * 8) = wv[j];
    }
    __syncthreads();

    gemm_compute<K, N, WM, WN, THREADS>(Xs, Ws, out, row0);
}

// merged layer-1 kernel: blocks [0, GEMM1_BLOCKS) do gemm1 (fp16 x), rest fill CSR.
__global__ void __launch_bounds__(512, 2)
k_l1(const __half* __restrict__ xh, const __half* __restrict__ W,
     __half* __restrict__ out, const int* __restrict__ ei) {
    extern __shared__ __half sm[];
    if (blockIdx.x < GEMM1_BLOCKS) {
        gemm_body<128, 128, 8, 2, 512>(xh, W, out, blockIdx.x, sm);
    } else {
        int i = (blockIdx.x - GEMM1_BLOCKS) * 512 + threadIdx.x;
        if (i < N_EDGES / 4) {
            int4 s4 = ((const int4*)ei)[i];
            int4 d4 = ((const int4*)(ei + N_EDGES))[i];
            g_csr[atomicAdd(&g_cursor[d4.x], 1)] = s4.x;
            g_csr[atomicAdd(&g_cursor[d4.y], 1)] = s4.y;
            g_csr[atomicAdd(&g_cursor[d4.z], 1)] = s4.z;
            g_csr[atomicAdd(&g_cursor[d4.w], 1)] = s4.w;
        }
    }
}

// ---------------- fused agg + next-layer GEMM ---------------------------------
// phase A: x_tile[nl] = fp16(relu((hin[n] + sum_nbr hin[s]) * dis + bias)) -> smem
// phase B: W staged at kernel start
// phase C: out = fp16((x_tile @ W) * dis)     (out = next layer's h)
template<int FIN, int NOUT, int WM, int WN>
__global__ void __launch_bounds__(256, 2)
k_aggemm(const __half* __restrict__ hin, const float* __restrict__ bias,
         const __half* __restrict__ Wn, __half* __restrict__ out) {
    constexpr int MT  = 128;
    constexpr int XS  = FIN + 8;
    constexpr int WS  = NOUT + 8;
    constexpr int LPE = FIN / 8;          // lanes per node
    constexpr int NPW = 32 / LPE;         // nodes per warp per pass
    constexpr int PASS_NODES = 8 * NPW;
    constexpr int PASSES = MT / PASS_NODES;
    constexpr int WLD = FIN * (NOUT / 8) / 256;

    extern __shared__ __half sm[];
    __half* Xs = sm;                      // MT x XS
    __half* Ws = sm + MT * XS;            // FIN x WS

    int tid  = threadIdx.x;
    int row0 = blockIdx.x * MT;

    // stage W (front-batched)
    uint4 wv[WLD];
    #pragma unroll
    for (int j = 0; j < WLD; j++)
        wv[j] = ((const uint4*)Wn)[tid + j * 256];
    #pragma unroll
    for (int j = 0; j < WLD; j++) {
        int i = tid + j * 256;
        int k = i / (NOUT / 8), c = i % (NOUT / 8);
        *(uint4*)(Ws + k * WS + c * 8) = wv[j];
    }

    int wid = tid >> 5, lane = tid & 31;
    int sub = lane / LPE, l = lane % LPE;
    const uint4* hv = (const uint4*)hin;

    #pragma unroll
    for (int pass = 0; pass < PASSES; pass++) {
        int nl = pass * PASS_NODES + wid * NPW + sub;
        int node = row0 + nl;
        if (node < N_NODES) {
            float2 acc[4];
            {
                uint4 sv = __ldg(&hv[(size_t)node * LPE + l]);
                __half2* p = (__half2*)&sv;
                #pragma unroll
                for (int k = 0; k < 4; k++) acc[k] = __half22float2(p[k]);
            }
            int rs = g_rowstart[node];
            int re = rs + g_degi[node];
            int j = rs;
            for (; j + 8 <= re; j += 8) {
                int4 ia = *(const int4*)(g_csr + j);
                int4 ib = *(const int4*)(g_csr + j + 4);
                uint4 v0 = __ldg(&hv[(size_t)ia.x * LPE + l]);
                uint4 v1 = __ldg(&hv[(size_t)ia.y * LPE + l]);
                uint4 v2 = __ldg(&hv[(size_t)ia.z * LPE + l]);
                uint4 v3 = __ldg(&hv[(size_t)ia.w * LPE + l]);
                uint4 v4 = __ldg(&hv[(size_t)ib.x * LPE + l]);
                uint4 v5 = __ldg(&hv[(size_t)ib.y * LPE + l]);
                uint4 v6 = __ldg(&hv[(size_t)ib.z * LPE + l]);
                uint4 v7 = __ldg(&hv[(size_t)ib.w * LPE + l]);
                acc_add(acc, v0); acc_add(acc, v1); acc_add(acc, v2); acc_add(acc, v3);
                acc_add(acc, v4); acc_add(acc, v5); acc_add(acc, v6); acc_add(acc, v7);
            }
            if (j + 4 <= re) {
                int4 ia = *(const int4*)(g_csr + j);
                uint4 v0 = __ldg(&hv[(size_t)ia.x * LPE + l]);
                uint4 v1 = __ldg(&hv[(size_t)ia.y * LPE + l]);
                uint4 v2 = __ldg(&hv[(size_t)ia.z * LPE + l]);
                uint4 v3 = __ldg(&hv[(size_t)ia.w * LPE + l]);
                acc_add(acc, v0); acc_add(acc, v1); acc_add(acc, v2); acc_add(acc, v3);
                j += 4;
            }
            for (; j < re; j++) {
                uint4 a = __ldg(&hv[(size_t)g_csr[j] * LPE + l]);
                acc_add(acc, a);
            }

            float dr = g_dis[node];
            float4 b0 = ((const float4*)bias)[l * 2];
            float4 b1 = ((const float4*)bias)[l * 2 + 1];
            float4 v0 = make_float4(fmaxf(fmaf(acc[0].x, dr, b0.x), 0.f),
                                    fmaxf(fmaf(acc[0].y, dr, b0.y), 0.f),
                                    fmaxf(fmaf(acc[1].x, dr, b0.z), 0.f),
                                    fmaxf(fmaf(acc[1].y, dr, b0.w), 0.f));
            float4 v1 = make_float4(fmaxf(fmaf(acc[2].x, dr, b1.x), 0.f),
                                    fmaxf(fmaf(acc[2].y, dr, b1.y), 0.f),
                                    fmaxf(fmaf(acc[3].x, dr, b1.z), 0.f),
                                    fmaxf(fmaf(acc[3].y, dr, b1.w), 0.f));
            uint4 o = cvt8(v0, v1);
            *(uint4*)(Xs + nl * XS + l * 8) = o;
        }
    }
    __syncthreads();

    gemm_compute<FIN, NOUT, WM, WN, 256>(Xs, Ws, out, row0);
}

// ---------------- final agg + mean pool (layer 3 output) ----------------------
__global__ void k_aggpool(const __half* __restrict__ h, const float* __restrict__ bias,
                          const int* __restrict__ batch) {
    constexpr int F = 32, LPE = 4, NPW = 8;
    int gw   = (blockIdx.x * 256 + threadIdx.x) >> 5;
    int lane = threadIdx.x & 31;
    int sub  = lane / LPE;
    int l    = lane % LPE;
    int node = gw * NPW + sub;
    if (node >= N_NODES) return;

    const uint4* hv = (const uint4*)h;

    float2 acc[4];
    {
        uint4 sv = __ldg(&hv[(size_t)node * LPE + l]);
        __half2* p = (__half2*)&sv;
        #pragma unroll
        for (int k = 0; k < 4; k++) acc[k] = __half22float2(p[k]);
    }

    int rs = g_rowstart[node];
    int re = rs + g_degi[node];
    int j = rs;
    for (; j + 8 <= re; j += 8) {
        int4 ia = *(const int4*)(g_csr + j);
        int4 ib = *(const int4*)(g_csr + j + 4);
        uint4 v0 = __ldg(&hv[(size_t)ia.x * LPE + l]);
        uint4 v1 = __ldg(&hv[(size_t)ia.y * LPE + l]);
        uint4 v2 = __ldg(&hv[(size_t)ia.z * LPE + l]);
        uint4 v3 = __ldg(&hv[(size_t)ia.w * LPE + l]);
        uint4 v4 = __ldg(&hv[(size_t)ib.x * LPE + l]);
        uint4 v5 = __ldg(&hv[(size_t)ib.y * LPE + l]);
        uint4 v6 = __ldg(&hv[(size_t)ib.z * LPE + l]);
        uint4 v7 = __ldg(&hv[(size_t)ib.w * LPE + l]);
        acc_add(acc, v0); acc_add(acc, v1); acc_add(acc, v2); acc_add(acc, v3);
        acc_add(acc, v4); acc_add(acc, v5); acc_add(acc, v6); acc_add(acc, v7);
    }
    if (j + 4 <= re) {
        int4 ia = *(const int4*)(g_csr + j);
        uint4 v0 = __ldg(&hv[(size_t)ia.x * LPE + l]);
        uint4 v1 = __ldg(&hv[(size_t)ia.y * LPE + l]);
        uint4 v2 = __ldg(&hv[(size_t)ia.z * LPE + l]);
        uint4 v3 = __ldg(&hv[(size_t)ia.w * LPE + l]);
        acc_add(acc, v0); acc_add(acc, v1); acc_add(acc, v2); acc_add(acc, v3);
        j += 4;
    }
    for (; j < re; j++) {
        uint4 a = __ldg(&hv[(size_t)g_csr[j] * LPE + l]);
        acc_add(acc, a);
    }

    float dr = g_dis[node];
    float4 b0 = ((const float4*)bias)[l * 2];
    float4 b1 = ((const float4*)bias)[l * 2 + 1];
    float4 v0 = make_float4(fmaxf(fmaf(acc[0].x, dr, b0.x), 0.f),
                            fmaxf(fmaf(acc[0].y, dr, b0.y), 0.f),
                            fmaxf(fmaf(acc[1].x, dr, b0.z), 0.f),
                            fmaxf(fmaf(acc[1].y, dr, b0.w), 0.f));
    float4 v1 = make_float4(fmaxf(fmaf(acc[2].x, dr, b1.x), 0.f),
                            fmaxf(fmaf(acc[2].y, dr, b1.y), 0.f),
                            fmaxf(fmaf(acc[3].x, dr, b1.z), 0.f),
                            fmaxf(fmaf(acc[3].y, dr, b1.w), 0.f));
    int g = batch[node];
    red_add_v4(g_pooled + g * 32 + l * 8, v0);
    red_add_v4(g_pooled + g * 32 + l * 8 + 4, v1);
}

// ---------------- head: out = (pooled/cnt) @ Wl + bl ----------------
__global__ void k_final(const float* __restrict__ Wl, const float* __restrict__ bl,
                        float* __restrict__ out) {
    int g = blockIdx.x;
    __shared__ float p[32];
    int tid = threadIdx.x;
    if (tid < 32) {
        float c = fmaxf(g_cnt[g], 1.0f);
        p[tid] = g_pooled[g * 32 + tid] / c;
    }
    __syncthreads();
    for (int j = tid; j < 768; j += 256) {
        float acc = bl[j];
        #pragma unroll
        for (int k = 0; k < 32; k++)
            acc = fmaf(p[k], Wl[k * 768 + j], acc);
        out[g * 768 + j] = acc;
    }
}

// ---------------- launch ----------------
extern "C" void kernel_launch(void* const* d_in, const int* in_sizes, int n_in,
                              void* d_out, int out_size) {
    const float* x  = (const float*)d_in[0];
    const float* W1 = (const float*)d_in[1];
    const float* b1 = (const float*)d_in[2];
    const float* W2 = (const float*)d_in[3];
    const float* b2 = (const float*)d_in[4];
    const float* W3 = (const float*)d_in[5];
    const float* b3 = (const float*)d_in[6];
    const float* Wl = (const float*)d_in[7];
    const float* bl = (const float*)d_in[8];
    const int* ei    = (const int*)d_in[9];
    const int* batch = (const int*)d_in[10];
    float* out = (float*)d_out;

    __half *p_xh, *p_w1h, *p_w2h, *p_w3h, *p_h1, *p_h2, *p_h3;
    cudaGetSymbolAddress((void**)&p_xh,  g_xh);
    cudaGetSymbolAddress((void**)&p_w1h, g_w1h);
    cudaGetSymbolAddress((void**)&p_w2h, g_w2h);
    cudaGetSymbolAddress((void**)&p_w3h, g_w3h);
    cudaGetSymbolAddress((void**)&p_h1,  g_h1);
    cudaGetSymbolAddress((void**)&p_h2,  g_h2);
    cudaGetSymbolAddress((void**)&p_h3,  g_h3);

    // smem: (128*(K+8) + K*(N+8)) * 2 bytes
    int s1 = (128 * 136 + 128 * 136) * 2;   // 69632
    int s2 = (128 * 136 + 128 * 72) * 2;    // 53248  (aggemm 128->64)
    int s3 = (128 * 72 + 64 * 40) * 2;      // 23552  (aggemm 64->32)
    cudaFuncSetAttribute(k_l1, cudaFuncAttributeMaxDynamicSharedMemorySize, s1);
    cudaFuncSetAttribute(k_aggemm<128, 64, 4, 2>,
                         cudaFuncAttributeMaxDynamicSharedMemorySize, s2);
    cudaFuncSetAttribute(k_aggemm<64, 32, 8, 1>,
                         cudaFuncAttributeMaxDynamicSharedMemorySize, s3);

    // ---- prep ----
    k_zero <<<NB, 256>>>(W1, W2, W3);
    k_count<<<625, 256>>>(ei, batch, x);
    k_scan <<<NB, 256>>>();

    // ---- layer 1: gemm1 (fp16 x) + CSR fill merged ----
    k_l1<<<GEMM1_BLOCKS + FILL_BLOCKS, 512, s1>>>(p_xh, p_w1h, p_h1, ei);

    // ---- layer 2: agg1 + gemm2 fused -> h2 ----
    k_aggemm<128, 64, 4, 2><<<GEMM1_BLOCKS, 256, s2>>>(p_h1, b1, p_w2h, p_h2);

    // ---- layer 3: agg2 + gemm3 fused -> h3 ----
    k_aggemm<64, 32, 8, 1><<<GEMM1_BLOCKS, 256, s3>>>(p_h2, b2, p_w3h, p_h3);

    // ---- agg3 + mean pool ----
    k_aggpool<<<625, 256>>>(p_h3, b3, batch);

    // ---- head ----
    k_final<<<N_GRAPHS, 256>>>(Wl, bl, out);
}

// round 17
// speedup vs baseline: 1.1753x; 1.1753x over previous
#include <cuda_runtime.h>
#include <cuda_fp16.h>
#include <cstdint>

#define N_NODES  40000
#define N_EDGES  640000
#define N_GRAPHS 256
#define NB 157            // ceil(40000/256) scan blocks
#define CSR_CAP 760000    // N_EDGES + N_NODES*3 worst-case pad-to-4
#define GEMM1_BLOCKS 313  // ceil(40000/128)
#define FILL_BLOCKS 313   // ceil(160000/512)

// ---------------- scratch (static __device__, no allocation) ----------------
__device__ __align__(16) int    g_degi[N_NODES];
__device__ __align__(16) int    g_rowstart[N_NODES];
__device__ __align__(16) int    g_cursor[N_NODES];
__device__ __align__(16) int    g_csr[CSR_CAP];
__device__ int    g_base;
__device__ __align__(16) float  g_dis[N_NODES];
__device__ __align__(16) __half g_xh[N_NODES * 128];
__device__ __align__(16) __half g_w1h[128 * 128];
__device__ __align__(16) __half g_w2h[128 * 64];
__device__ __align__(16) __half g_w3h[64 * 32];
__device__ __align__(16) __half g_h1[N_NODES * 128];
__device__ __align__(16) __half g_x2[N_NODES * 128];
__device__ __align__(16) __half g_h2[N_NODES * 64];
__device__ __align__(16) __half g_x3[N_NODES * 64];
__device__ __align__(16) __half g_h3[N_NODES * 32];
__device__ __align__(16) float  g_pooled[N_GRAPHS * 32];
__device__ __align__(16) float  g_cnt[N_GRAPHS];

// ---------------- helpers ----------------
__device__ __forceinline__ void red_add_v4(float* addr, float4 v) {
    asm volatile("red.global.add.v4.f32 [%0], {%1, %2, %3, %4};"
                 :: "l"(addr), "f"(v.x), "f"(v.y), "f"(v.z), "f"(v.w)
                 : "memory");
}
__device__ __forceinline__ unsigned h2_bits(__half2 h) {
    unsigned u;
    *(__half2*)&u = h;
    return u;
}
__device__ __forceinline__ uint4 cvt8(float4 a, float4 b) {
    uint4 o;
    o.x = h2_bits(__floats2half2_rn(a.x, a.y));
    o.y = h2_bits(__floats2half2_rn(a.z, a.w));
    o.z = h2_bits(__floats2half2_rn(b.x, b.y));
    o.w = h2_bits(__floats2half2_rn(b.z, b.w));
    return o;
}
__device__ __forceinline__ void acc_add(float2 acc[4], uint4 v) {
    __half2* p = (__half2*)&v;
    #pragma unroll
    for (int k = 0; k < 4; k++) {
        float2 f = __half22float2(p[k]);
        acc[k].x += f.x; acc[k].y += f.y;
    }
}
__device__ __forceinline__ void ldsm_x4(unsigned* r, const __half* p) {
    unsigned a = (unsigned)__cvta_generic_to_shared(p);
    asm volatile("ldmatrix.sync.aligned.m8n8.x4.shared.b16 {%0,%1,%2,%3}, [%4];"
                 : "=r"(r[0]), "=r"(r[1]), "=r"(r[2]), "=r"(r[3]) : "r"(a));
}
__device__ __forceinline__ void ldsm_x4_t(unsigned* r, const __half* p) {
    unsigned a = (unsigned)__cvta_generic_to_shared(p);
    asm volatile("ldmatrix.sync.aligned.m8n8.x4.trans.shared.b16 {%0,%1,%2,%3}, [%4];"
                 : "=r"(r[0]), "=r"(r[1]), "=r"(r[2]), "=r"(r[3]) : "r"(a));
}
__device__ __forceinline__ void mma16816(float* d, const unsigned* a, const unsigned* b) {
    asm volatile(
        "mma.sync.aligned.m16n8k16.row.col.f32.f16.f16.f32 "
        "{%0,%1,%2,%3}, {%4,%5,%6,%7}, {%8,%9}, {%0,%1,%2,%3};"
        : "+f"(d[0]), "+f"(d[1]), "+f"(d[2]), "+f"(d[3])
        : "r"(a[0]), "r"(a[1]), "r"(a[2]), "r"(a[3]), "r"(b[0]), "r"(b[1]));
}

// ---------------- prep ----------------
// zero scratch + convert all three W matrices to fp16 (no extra launch)
__global__ void k_zero(const float* __restrict__ W1, const float* __restrict__ W2,
                       const float* __restrict__ W3) {
    int i = blockIdx.x * blockDim.x + threadIdx.x;
    if (i < N_NODES) g_degi[i] = 0;
    if (i < N_GRAPHS * 32) g_pooled[i] = 0.f;
    if (i < N_GRAPHS) g_cnt[i] = 0.f;
    if (i == 0) g_base = 0;
    if (i < 8192)
        ((__half2*)g_w1h)[i] = __float22half2_rn(((const float2*)W1)[i]);
    else if (i < 12288)
        ((__half2*)g_w2h)[i - 8192] = __float22half2_rn(((const float2*)W2)[i - 8192]);
    else if (i < 13312)
        ((__half2*)g_w3h)[i - 12288] = __float22half2_rn(((const float2*)W3)[i - 12288]);
}

// degree count + batch count + x fp32->fp16 convert (atomic latency overlapped
// with streaming conversion). grid 625*256 = 160000 threads.
__global__ void k_count(const int* __restrict__ ei, const int* __restrict__ batch,
                        const float* __restrict__ x) {
    int i = blockIdx.x * blockDim.x + threadIdx.x;
    int4 d4 = ((const int4*)(ei + N_EDGES))[i];
    atomicAdd(&g_degi[d4.x], 1);
    atomicAdd(&g_degi[d4.y], 1);
    atomicAdd(&g_degi[d4.z], 1);
    atomicAdd(&g_degi[d4.w], 1);
    if (i < N_NODES) atomicAdd(&g_cnt[batch[i]], 1.0f);
    #pragma unroll
    for (int j = 0; j < 4; j++) {
        int idx = i + j * 160000;              // 640000 uint4 total
        float4 a = ((const float4*)x)[(size_t)idx * 2];
        float4 b = ((const float4*)x)[(size_t)idx * 2 + 1];
        ((uint4*)g_xh)[idx] = cvt8(a, b);
    }
}

// single-kernel scan over PADDED degrees (segments rounded to 4 ints)
__global__ void k_scan() {
    int t = threadIdx.x, i = blockIdx.x * 256 + t;
    int lane = t & 31, w = t >> 5;
    int v  = (i < N_NODES) ? g_degi[i] : 0;
    int pv = (v + 3) & ~3;

    int sv = pv;
    #pragma unroll
    for (int off = 1; off < 32; off <<= 1) {
        int n = __shfl_up_sync(0xffffffffu, sv, off);
        if (lane >= off) sv += n;
    }
    __shared__ int ws[8];
    if (lane == 31) ws[w] = sv;
    __syncthreads();
    if (w == 0 && lane < 8) {
        int x = ws[lane];
        #pragma unroll
        for (int off = 1; off < 8; off <<= 1) {
            int n = __shfl_up_sync(0xffu, x, off);
            if (lane >= off) x += n;
        }
        ws[lane] = x;
    }
    __syncthreads();
    int incl = sv + (w ? ws[w - 1] : 0);

    __shared__ int base;
    if (t == 255) base = atomicAdd(&g_base, incl);
    __syncthreads();

    if (i < N_NODES) {
        int ex = base + incl - pv;
        g_rowstart[i] = ex;
        g_cursor[i]   = ex;
        g_dis[i]      = rsqrtf((float)v + 1.0f);
    }
}

// ---------------- GEMM body (fp16 in, fp16 W, batched staging loads) --------
template<int K, int N, int WM, int WN, int THREADS>
__device__ __forceinline__ void gemm_body(const __half* __restrict__ in,
                                          const __half* __restrict__ W,
                                          __half* __restrict__ out,
                                          int tile, __half* sm) {
    constexpr int MT  = 128;
    constexpr int XS  = K + 8;
    constexpr int WS  = N + 8;
    constexpr int MW  = MT / WM;
    constexpr int NW  = N / WN;
    constexpr int MTL = MW / 16;
    constexpr int NTL = NW / 8;
    constexpr int XLD = MT * (K / 8) / THREADS;
    constexpr int WLD = K * (N / 8) / THREADS;
    static_assert(WM * WN == THREADS / 32, "warp layout");
    static_assert(MTL >= 1 && NTL >= 2 && NTL % 2 == 0, "tile shape");

    __half* Xs = sm;                 // MT x XS
    __half* Ws = sm + MT * XS;       // K x WS

    int tid  = threadIdx.x;
    int row0 = tile * MT;
    int rows = N_NODES - row0; if (rows > MT) rows = MT;

    // phase 1: front-batched global loads
    uint4 xv[XLD];
    #pragma unroll
    for (int j = 0; j < XLD; j++) {
        int i = tid + j * THREADS;
        int r = i / (K / 8);
        xv[j] = make_uint4(0, 0, 0, 0);
        if (r < rows)
            xv[j] = ((const uint4*)in)[(size_t)row0 * (K / 8) + i];
    }
    uint4 wv[WLD];
    #pragma unroll
    for (int j = 0; j < WLD; j++)
        wv[j] = ((const uint4*)W)[tid + j * THREADS];

    // phase 2: smem stores
    #pragma unroll
    for (int j = 0; j < XLD; j++) {
        int i = tid + j * THREADS;
        int r = i / (K / 8), c = i % (K / 8);
        *(uint4*)(Xs + r * XS + c * 8) = xv[j];
    }
    #pragma unroll
    for (int j = 0; j < WLD; j++) {
        int i = tid + j * THREADS;
        int k = i / (N / 8), c = i % (N / 8);
        *(uint4*)(Ws + k * WS + c * 8) = wv[j];
    }
    __syncthreads();

    int wid = tid >> 5, lane = tid & 31;
    int wm = wid % WM, wn = wid / WM;
    int mbase = wm * MW, nbase = wn * NW;

    float acc[MTL][NTL][4];
    #pragma unroll
    for (int mt = 0; mt < MTL; mt++)
        #pragma unroll
        for (int nt = 0; nt < NTL; nt++)
            acc[mt][nt][0] = acc[mt][nt][1] = acc[mt][nt][2] = acc[mt][nt][3] = 0.f;

    #pragma unroll
    for (int k0 = 0; k0 < K; k0 += 16) {
        unsigned af[MTL][4];
        unsigned bf[NTL][2];
        #pragma unroll
        for (int mt = 0; mt < MTL; mt++) {
            const __half* p = Xs + (mbase + mt * 16 + (lane & 15)) * XS
                                 + k0 + ((lane >> 4) << 3);
            ldsm_x4(af[mt], p);
        }
        #pragma unroll
        for (int p2 = 0; p2 < NTL / 2; p2++) {
            const __half* p = Ws + (k0 + (lane & 15)) * WS
                                 + nbase + p2 * 16 + ((lane >> 4) << 3);
            ldsm_x4_t(&bf[p2 * 2][0], p);
        }
        #pragma unroll
        for (int mt = 0; mt < MTL; mt++)
            #pragma unroll
            for (int nt = 0; nt < NTL; nt++)
                mma16816(acc[mt][nt], af[mt], bf[nt]);
    }

    int gr = lane >> 2, tc = (lane & 3) << 1;
    #pragma unroll
    for (int mt = 0; mt < MTL; mt++) {
        int rA = mbase + mt * 16 + gr;
        int rB = rA + 8;
        bool okA = rA < rows, okB = rB < rows;
        float dA = okA ? g_dis[row0 + rA] : 0.f;
        float dB = okB ? g_dis[row0 + rB] : 0.f;
        #pragma unroll
        for (int nt = 0; nt < NTL; nt++) {
            int col = nbase + nt * 8 + tc;
            if (okA)
                *(__half2*)(out + (size_t)(row0 + rA) * N + col) =
                    __floats2half2_rn(acc[mt][nt][0] * dA, acc[mt][nt][1] * dA);
            if (okB)
                *(__half2*)(out + (size_t)(row0 + rB) * N + col) =
                    __floats2half2_rn(acc[mt][nt][2] * dB, acc[mt][nt][3] * dB);
        }
    }
}

// standalone GEMM (layers 2, 3)
template<int K, int N, int WM, int WN, int THREADS>
__global__ void __launch_bounds__(THREADS, 2)
k_hgemm(const __half* __restrict__ in, const __half* __restrict__ W,
        __half* __restrict__ out) {
    extern __shared__ __half sm[];
    gemm_body<K, N, WM, WN, THREADS>(in, W, out, blockIdx.x, sm);
}

// merged layer-1 kernel: blocks [0, GEMM1_BLOCKS) do gemm1 (fp16 x), rest fill CSR.
__global__ void __launch_bounds__(512, 2)
k_l1(const __half* __restrict__ xh, const __half* __restrict__ W,
     __half* __restrict__ out, const int* __restrict__ ei) {
    extern __shared__ __half sm[];
    if (blockIdx.x < GEMM1_BLOCKS) {
        gemm_body<128, 128, 8, 2, 512>(xh, W, out, blockIdx.x, sm);
    } else {
        int i = (blockIdx.x - GEMM1_BLOCKS) * 512 + threadIdx.x;
        if (i < N_EDGES / 4) {
            int4 s4 = ((const int4*)ei)[i];
            int4 d4 = ((const int4*)(ei + N_EDGES))[i];
            g_csr[atomicAdd(&g_cursor[d4.x], 1)] = s4.x;
            g_csr[atomicAdd(&g_cursor[d4.y], 1)] = s4.y;
            g_csr[atomicAdd(&g_cursor[d4.z], 1)] = s4.z;
            g_csr[atomicAdd(&g_cursor[d4.w], 1)] = s4.w;
        }
    }
}

// ---------------- CSR aggregation: out = fp16(relu((h[n] + sum h[s]) * dis + b)) ----------------
template<int F, bool POOL>
__global__ void k_agg(const __half* __restrict__ h, const float* __restrict__ bias,
                      const int* __restrict__ batch, __half* __restrict__ out) {
    constexpr int LPE = F / 8;        // lanes per node (8 halves each)
    constexpr int NPW = 32 / LPE;
    int gw   = (blockIdx.x * 256 + threadIdx.x) >> 5;
    int lane = threadIdx.x & 31;
    int sub  = lane / LPE;
    int l    = lane % LPE;
    int node = gw * NPW + sub;
    if (node >= N_NODES) return;

    const uint4* hv = (const uint4*)h;

    float2 acc[4];
    {
        uint4 sv = __ldg(&hv[(size_t)node * LPE + l]);
        __half2* p = (__half2*)&sv;
        #pragma unroll
        for (int k = 0; k < 4; k++) acc[k] = __half22float2(p[k]);
    }

    int rs = g_rowstart[node];
    int re = rs + g_degi[node];

    int j = rs;
    for (; j + 8 <= re; j += 8) {
        int4 ia = *(const int4*)(g_csr + j);
        int4 ib = *(const int4*)(g_csr + j + 4);
        uint4 v0 = __ldg(&hv[(size_t)ia.x * LPE + l]);
        uint4 v1 = __ldg(&hv[(size_t)ia.y * LPE + l]);
        uint4 v2 = __ldg(&hv[(size_t)ia.z * LPE + l]);
        uint4 v3 = __ldg(&hv[(size_t)ia.w * LPE + l]);
        uint4 v4 = __ldg(&hv[(size_t)ib.x * LPE + l]);
        uint4 v5 = __ldg(&hv[(size_t)ib.y * LPE + l]);
        uint4 v6 = __ldg(&hv[(size_t)ib.z * LPE + l]);
        uint4 v7 = __ldg(&hv[(size_t)ib.w * LPE + l]);
        acc_add(acc, v0); acc_add(acc, v1); acc_add(acc, v2); acc_add(acc, v3);
        acc_add(acc, v4); acc_add(acc, v5); acc_add(acc, v6); acc_add(acc, v7);
    }
    if (j + 4 <= re) {
        int4 ia = *(const int4*)(g_csr + j);
        uint4 v0 = __ldg(&hv[(size_t)ia.x * LPE + l]);
        uint4 v1 = __ldg(&hv[(size_t)ia.y * LPE + l]);
        uint4 v2 = __ldg(&hv[(size_t)ia.z * LPE + l]);
        uint4 v3 = __ldg(&hv[(size_t)ia.w * LPE + l]);
        acc_add(acc, v0); acc_add(acc, v1); acc_add(acc, v2); acc_add(acc, v3);
        j += 4;
    }
    for (; j < re; j++) {
        uint4 a = __ldg(&hv[(size_t)g_csr[j] * LPE + l]);
        acc_add(acc, a);
    }

    float dr = g_dis[node];
    float4 b0 = ((const float4*)bias)[l * 2];
    float4 b1 = ((const float4*)bias)[l * 2 + 1];
    float4 v0 = make_float4(fmaxf(fmaf(acc[0].x, dr, b0.x), 0.f),
                            fmaxf(fmaf(acc[0].y, dr, b0.y), 0.f),
                            fmaxf(fmaf(acc[1].x, dr, b0.z), 0.f),
                            fmaxf(fmaf(acc[1].y, dr, b0.w), 0.f));
    float4 v1 = make_float4(fmaxf(fmaf(acc[2].x, dr, b1.x), 0.f),
                            fmaxf(fmaf(acc[2].y, dr, b1.y), 0.f),
                            fmaxf(fmaf(acc[3].x, dr, b1.z), 0.f),
                            fmaxf(fmaf(acc[3].y, dr, b1.w), 0.f));
    if (POOL) {
        int g = batch[node];
        red_add_v4(g_pooled + g * 32 + l * 8, v0);
        red_add_v4(g_pooled + g * 32 + l * 8 + 4, v1);
    } else {
        uint4 o = cvt8(v0, v1);
        ((uint4*)out)[(size_t)node * LPE + l] = o;
    }
}

// ---------------- head: out = (pooled/cnt) @ Wl + bl ----------------
__global__ void k_final(const float* __restrict__ Wl, const float* __restrict__ bl,
                        float* __restrict__ out) {
    int g = blockIdx.x;
    __shared__ float p[32];
    int tid = threadIdx.x;
    if (tid < 32) {
        float c = fmaxf(g_cnt[g], 1.0f);
        p[tid] = g_pooled[g * 32 + tid] / c;
    }
    __syncthreads();
    for (int j = tid; j < 768; j += 256) {
        float acc = bl[j];
        #pragma unroll
        for (int k = 0; k < 32; k++)
            acc = fmaf(p[k], Wl[k * 768 + j], acc);
        out[g * 768 + j] = acc;
    }
}

// ---------------- launch ----------------
extern "C" void kernel_launch(void* const* d_in, const int* in_sizes, int n_in,
                              void* d_out, int out_size) {
    const float* x  = (const float*)d_in[0];
    const float* W1 = (const float*)d_in[1];
    const float* b1 = (const float*)d_in[2];
    const float* W2 = (const float*)d_in[3];
    const float* b2 = (const float*)d_in[4];
    const float* W3 = (const float*)d_in[5];
    const float* b3 = (const float*)d_in[6];
    const float* Wl = (const float*)d_in[7];
    const float* bl = (const float*)d_in[8];
    const int* ei    = (const int*)d_in[9];
    const int* batch = (const int*)d_in[10];
    float* out = (float*)d_out;

    __half *p_xh, *p_w1h, *p_w2h, *p_w3h, *p_h1, *p_x2, *p_h2, *p_x3, *p_h3;
    cudaGetSymbolAddress((void**)&p_xh,  g_xh);
    cudaGetSymbolAddress((void**)&p_w1h, g_w1h);
    cudaGetSymbolAddress((void**)&p_w2h, g_w2h);
    cudaGetSymbolAddress((void**)&p_w3h, g_w3h);
    cudaGetSymbolAddress((void**)&p_h1,  g_h1);
    cudaGetSymbolAddress((void**)&p_x2,  g_x2);
    cudaGetSymbolAddress((void**)&p_h2,  g_h2);
    cudaGetSymbolAddress((void**)&p_x3,  g_x3);
    cudaGetSymbolAddress((void**)&p_h3,  g_h3);

    // smem: (128*(K+8) + K*(N+8)) * 2 bytes
    int s1 = (128 * 136 + 128 * 136) * 2;   // 69632
    int s2 = (128 * 136 + 128 * 72) * 2;    // 53248
    int s3 = (128 * 72 + 64 * 40) * 2;      // 23552
    cudaFuncSetAttribute(k_l1, cudaFuncAttributeMaxDynamicSharedMemorySize, s1);
    cudaFuncSetAttribute(k_hgemm<128, 64, 8, 2, 512>,
                         cudaFuncAttributeMaxDynamicSharedMemorySize, s2);
    cudaFuncSetAttribute(k_hgemm<64, 32, 8, 1, 256>,
                         cudaFuncAttributeMaxDynamicSharedMemorySize, s3);

    int mblocks = (N_NODES + 127) / 128;    // 313

    // ---- prep (W convert in k_zero, x convert in k_count) ----
    k_zero <<<NB, 256>>>(W1, W2, W3);
    k_count<<<625, 256>>>(ei, batch, x);
    k_scan <<<NB, 256>>>();

    // ---- layer 1: gemm1 (fp16 x) + CSR fill merged ----
    k_l1<<<GEMM1_BLOCKS + FILL_BLOCKS, 512, s1>>>(p_xh, p_w1h, p_h1, ei);
    k_agg<128, false><<<2500, 256>>>(p_h1, b1, batch, p_x2);

    // ---- layer 2: 128 -> 64 ----
    k_hgemm<128, 64, 8, 2, 512><<<mblocks, 512, s2>>>(p_x2, p_w2h, p_h2);
    k_agg<64, false><<<1250, 256>>>(p_h2, b2, batch, p_x3);

    // ---- layer 3: 64 -> 32 (pool fused) ----
    k_hgemm<64, 32, 8, 1, 256><<<mblocks, 256, s3>>>(p_x3, p_w3h, p_h3);
    k_agg<32, true><<<625, 256>>>(p_h3, b3, batch, nullptr);

    // ---- head ----
    k_final<<<N_GRAPHS, 256>>>(Wl, bl, out);
}